// round 12
// baseline (speedup 1.0000x reference)
#include <cuda_runtime.h>

#define FULL 0xFFFFFFFFu
#define NLOG2E  (-1.4426950408889634f)
#define N2LOG2E (-2.8853900817779268f)

__device__ __forceinline__ unsigned long long pack2(float a, float b) {
    unsigned long long r;
    asm("mov.b64 %0, {%1, %2};" : "=l"(r) : "f"(a), "f"(b));
    return r;
}
__device__ __forceinline__ void unpack2(unsigned long long p, float& a, float& b) {
    asm("mov.b64 {%0, %1}, %2;" : "=f"(a), "=f"(b) : "l"(p));
}
__device__ __forceinline__ unsigned long long fma2(unsigned long long a,
                                                   unsigned long long b,
                                                   unsigned long long c) {
    unsigned long long d;
    asm("fma.rn.f32x2 %0, %1, %2, %3;" : "=l"(d) : "l"(a), "l"(b), "l"(c));
    return d;
}
__device__ __forceinline__ unsigned long long add2(unsigned long long a,
                                                   unsigned long long b) {
    unsigned long long d;
    asm("add.rn.f32x2 %0, %1, %2;" : "=l"(d) : "l"(a), "l"(b));
    return d;
}
__device__ __forceinline__ float ex2f(float x) {
    float r; asm("ex2.approx.f32 %0, %1;" : "=f"(r) : "f"(x)); return r;
}
__device__ __forceinline__ float rcpf(float x) {
    float r; asm("rcp.approx.f32 %0, %1;" : "=f"(r) : "f"(x)); return r;
}
__device__ __forceinline__ float fast_sigmoid(float x) {       // plain domain
    return rcpf(1.0f + ex2f(x * NLOG2E));
}

// One CTA per TWO batches, 160 threads, grid 128 (one CTA/SM, single wave).
// Round 12: batch0's nonlinear tail is WOVEN INTO batch1's fma burst in
// source order (sigmoid ops between fma groups, STS after all of burst1's
// LDS), so its ~120-cycle latency chain overlaps fma issue by construction
// instead of relying on ptxas hoisting (which R7/R9 showed never happens).
// Weights pre-scaled by -log2e (j column by -2log2e, forget bias folded),
// removing the leading FMUL from every sigmoid: sigma = RCP(1 + EX2(z)).
// Threads 0..127: layer-0; thread = (unit u = t>>1, type = t&1); type0 owns
// (i,j), type1 owns (f,o); weights register-resident f32x2.
// Threads 128..159 (warp 4): layer-1 (units=1) + dense for both batches
// (lane halves), one step lagged. One __syncthreads per step.
__global__ __launch_bounds__(160, 1)
void lstm_stack_kernel(const float* __restrict__ x,
                       const float* __restrict__ W0,
                       const float* __restrict__ b0,
                       const float* __restrict__ W1,
                       const float* __restrict__ b1,
                       const float* __restrict__ Wd,
                       const float* __restrict__ bd,
                       float* __restrict__ out)
{
    constexpr int T = 2048;

    const int bb   = blockIdx.x;      // batch pair
    const int tid  = threadIdx.x;
    const int lane = tid & 31;
    const int wid  = tid >> 5;

    __shared__ __align__(16) float x_sh[2][T];
    __shared__ __align__(16) float h_sh[2][2][64];   // [buffer][batch][unit]
    __shared__ float red[5];
    __shared__ float inv_sh[2];

    // ---- Phase 0: load both x tiles, l2-normalize over time ----
    for (int bi = 0; bi < 2; ++bi) {
        const float* xb = x + (2 * bb + bi) * T;
        float ps = 0.f;
        for (int i = tid; i < T; i += 160) {
            float v = xb[i];
            x_sh[bi][i] = v;
            ps = fmaf(v, v, ps);
        }
        #pragma unroll
        for (int o = 16; o > 0; o >>= 1) ps += __shfl_xor_sync(FULL, ps, o);
        if (lane == 0) red[wid] = ps;
        __syncthreads();
        if (tid == 0) {
            float s = 0.f;
            #pragma unroll
            for (int i = 0; i < 5; ++i) s += red[i];
            inv_sh[bi] = rsqrtf(fmaxf(s, 1e-12f));
        }
        __syncthreads();               // also protects red[] reuse
    }
    {
        float i0 = inv_sh[0], i1 = inv_sh[1];
        for (int i = tid; i < T; i += 160) {
            x_sh[0][i] *= i0;
            x_sh[1][i] *= i1;
        }
    }
    if (tid < 128) ((float*)h_sh[0])[tid] = 0.f;   // h_{-1} = 0, both batches
    // (ordered by the sync at the top of the main loop)

    // ---- Per-thread persistent state / weights (pre-scaled) ----
    const int u    = tid >> 1;
    const int type = tid & 1;           // 0: (i,j)   1: (f,o)
    unsigned long long wpa[32], wpb[32];
    float wxa = 0.f, wxb = 0.f, ba = 0.f, bb2 = 0.f;
    float c0_0 = 0.f, c0_1 = 0.f;

    // layer-1 (warp 4) state: lanes 0-15 -> batch0, 16-31 -> batch1
    const int l1b  = lane >> 4;
    const int l1g  = lane & 3;
    const int l1bk = (lane >> 2) & 3;
    float w1r[16];
    float w1h = 0.f, b1v = 0.f, wdv = 0.f, bdv = 0.f;
    float c1 = 0.f, h1 = 0.f;

    if (tid < 128) {
        const int ca = u + (type ? 128 : 0);   // i or f column
        const int cb = ca + 64;                // j or o column
        const float sca = NLOG2E;                         // i / f
        const float scb = type ? NLOG2E : N2LOG2E;        // o / j (tanh via 2j)
        wxa = W0[ca] * sca;
        wxb = W0[cb] * scb;
        ba  = (b0[ca] + (type ? 1.0f : 0.0f)) * sca;      // fold FORGET_BIAS
        bb2 = b0[cb] * scb;
        #pragma unroll
        for (int p = 0; p < 32; ++p) {
            wpa[p] = pack2(W0[(1 + 2 * p) * 256 + ca] * sca,
                           W0[(2 + 2 * p) * 256 + ca] * sca);
            wpb[p] = pack2(W0[(1 + 2 * p) * 256 + cb] * scb,
                           W0[(2 + 2 * p) * 256 + cb] * scb);
        }
    } else {
        #pragma unroll
        for (int j = 0; j < 16; ++j)
            w1r[j] = W1[(l1bk + 4 * j) * 4 + l1g];
        w1h = W1[64 * 4 + l1g];
        b1v = b1[l1g];
        wdv = Wd[0];
        bdv = bd[0];
    }

    // ---- Main recurrence: t = 0..T. Layer-0 active for t<T, layer-1
    // processes step t-1 (final iteration drains layer-1). ----
    #pragma unroll 1
    for (int t = 0; t <= T; ++t) {
        const int tt = (t < T) ? t : 0;
        const float xt0 = x_sh[0][tt];   // read-only prefetch
        const float xt1 = x_sh[1][tt];
        __syncthreads();                 // h_sh[t&1] = h_{t-1} now valid
        const int cur = t & 1;
        if (tid < 128) {
            if (t < T) {
                const ulonglong2* hp0 = (const ulonglong2*)h_sh[cur][0];
                const ulonglong2* hp1 = (const ulonglong2*)h_sh[cur][1];
                unsigned long long zero = pack2(0.f, 0.f);

                // ---- burst 0 (batch 0 dot, scaled domain) ----
                unsigned long long a0 = pack2(fmaf(xt0, wxa, ba), 0.f);
                unsigned long long a1 = zero;
                unsigned long long e0 = pack2(fmaf(xt0, wxb, bb2), 0.f);
                unsigned long long e1 = zero;
                #pragma unroll
                for (int i = 0; i < 16; ++i) {
                    ulonglong2 hv = hp0[i];
                    a0 = fma2(hv.x, wpa[2 * i],     a0);
                    a1 = fma2(hv.y, wpa[2 * i + 1], a1);
                    e0 = fma2(hv.x, wpb[2 * i],     e0);
                    e1 = fma2(hv.y, wpb[2 * i + 1], e1);
                }
                float za0, zb0;
                {
                    float lo, hi;
                    unpack2(add2(a0, a1), lo, hi); za0 = lo + hi;
                    unpack2(add2(e0, e1), lo, hi); zb0 = lo + hi;
                }

                // ---- tail0 part A: launch sigmoid EX2s ----
                float ea0 = ex2f(za0);
                float eb0 = ex2f(zb0);

                // ---- burst 1, first half ----
                unsigned long long f0 = pack2(fmaf(xt1, wxa, ba), 0.f);
                unsigned long long f1 = zero;
                unsigned long long g0 = pack2(fmaf(xt1, wxb, bb2), 0.f);
                unsigned long long g1 = zero;
                #pragma unroll
                for (int i = 0; i < 8; ++i) {
                    ulonglong2 hv = hp1[i];
                    f0 = fma2(hv.x, wpa[2 * i],     f0);
                    f1 = fma2(hv.y, wpa[2 * i + 1], f1);
                    g0 = fma2(hv.x, wpb[2 * i],     g0);
                    g1 = fma2(hv.y, wpb[2 * i + 1], g1);
                }

                // ---- tail0 part B: finish sigmoids, exchange ----
                float sa0 = rcpf(1.0f + ea0);               // sigma(i) / sigma(f+1)
                float sb0 = rcpf(1.0f + eb0);               // sigma(2j) / sigma(o)
                float rb0 = type ? sb0 : fmaf(2.f, sb0, -1.f);   // tanh(j) on type0
                float send0 = type ? sa0 : (sa0 * rb0);
                float recv0 = __shfl_xor_sync(FULL, send0, 1);

                // ---- burst 1, second half ----
                #pragma unroll
                for (int i = 8; i < 16; ++i) {
                    ulonglong2 hv = hp1[i];
                    f0 = fma2(hv.x, wpa[2 * i],     f0);
                    f1 = fma2(hv.y, wpa[2 * i + 1], f1);
                    g0 = fma2(hv.x, wpb[2 * i],     g0);
                    g1 = fma2(hv.y, wpb[2 * i + 1], g1);
                }

                // ---- tail0 part C: cell update + tanh + publish ----
                {
                    float fg0  = type ? sa0 : recv0;
                    float inc0 = type ? recv0 : send0;
                    c0_0 = fmaf(fg0, c0_0, inc0);
                    float tc0 = fmaf(2.f, rcpf(1.0f + ex2f(c0_0 * N2LOG2E)), -1.f);
                    if (type) h_sh[cur ^ 1][0][u] = rb0 * tc0;   // rb0 = sigma(o)
                }

                // ---- tail 1 (exposed) ----
                float za1, zb1;
                {
                    float lo, hi;
                    unpack2(add2(f0, f1), lo, hi); za1 = lo + hi;
                    unpack2(add2(g0, g1), lo, hi); zb1 = lo + hi;
                }
                float sa1 = rcpf(1.0f + ex2f(za1));
                float sb1 = rcpf(1.0f + ex2f(zb1));
                float rb1 = type ? sb1 : fmaf(2.f, sb1, -1.f);
                float send1 = type ? sa1 : (sa1 * rb1);
                float recv1 = __shfl_xor_sync(FULL, send1, 1);
                float fg1  = type ? sa1 : recv1;
                float inc1 = type ? recv1 : send1;
                c0_1 = fmaf(fg1, c0_1, inc1);
                float tc1 = fmaf(2.f, rcpf(1.0f + ex2f(c0_1 * N2LOG2E)), -1.f);
                if (type) h_sh[cur ^ 1][1][u] = rb1 * tc1;
            }
        } else {
            if (t >= 1) {
                // layer-1 for step s = t-1, input h_sh[cur][l1b]
                const float* hv = h_sh[cur][l1b];
                float p0 = 0.f, p1 = 0.f;
                #pragma unroll
                for (int j = 0; j < 8; ++j) {
                    p0 = fmaf(hv[l1bk + 4 * (2 * j)],     w1r[2 * j],     p0);
                    p1 = fmaf(hv[l1bk + 4 * (2 * j + 1)], w1r[2 * j + 1], p1);
                }
                float p = p0 + p1;
                p += __shfl_xor_sync(FULL, p, 4);    // stays within 16-lane half
                p += __shfl_xor_sync(FULL, p, 8);
                float z1 = fmaf(h1, w1h, p + b1v);

                float zz = (l1g == 2) ? (z1 + 1.0f) : z1;
                float sv = (l1g == 1) ? (zz + zz) : zz;
                float sg = fast_sigmoid(sv);
                float r  = (l1g == 1) ? fmaf(2.f, sg, -1.f) : sg;

                float ri = __shfl_sync(FULL, r, 0, 4);
                float rj = __shfl_sync(FULL, r, 1, 4);
                float rf = __shfl_sync(FULL, r, 2, 4);
                float ro = __shfl_sync(FULL, r, 3, 4);
                c1 = fmaf(rf, c1, ri * rj);
                float th = fmaf(2.f, fast_sigmoid(c1 + c1), -1.f);
                h1 = ro * th;
                if ((lane & 15) == 0)
                    out[(2 * bb + l1b) * T + (t - 1)] = fmaf(h1, wdv, bdv);
            }
        }
    }
}

extern "C" void kernel_launch(void* const* d_in, const int* in_sizes, int n_in,
                              void* d_out, int out_size) {
    const float* x  = (const float*)d_in[0];
    const float* W0 = (const float*)d_in[1];
    const float* b0 = (const float*)d_in[2];
    const float* W1 = (const float*)d_in[3];
    const float* b1 = (const float*)d_in[4];
    const float* Wd = (const float*)d_in[5];
    const float* bd = (const float*)d_in[6];
    float* out = (float*)d_out;
    lstm_stack_kernel<<<128, 160>>>(x, W0, b0, W1, b1, Wd, bd, out);
}

// round 13
// speedup vs baseline: 1.2279x; 1.2279x over previous
#include <cuda_runtime.h>

#define FULL 0xFFFFFFFFu
#define NLOG2E  (-1.4426950408889634f)
#define N2LOG2E (-2.8853900817779268f)

__device__ __forceinline__ unsigned long long pack2(float a, float b) {
    unsigned long long r;
    asm("mov.b64 %0, {%1, %2};" : "=l"(r) : "f"(a), "f"(b));
    return r;
}
__device__ __forceinline__ void unpack2(unsigned long long p, float& a, float& b) {
    asm("mov.b64 {%0, %1}, %2;" : "=f"(a), "=f"(b) : "l"(p));
}
__device__ __forceinline__ unsigned long long fma2(unsigned long long a,
                                                   unsigned long long b,
                                                   unsigned long long c) {
    unsigned long long d;
    asm("fma.rn.f32x2 %0, %1, %2, %3;" : "=l"(d) : "l"(a), "l"(b), "l"(c));
    return d;
}
__device__ __forceinline__ unsigned long long add2(unsigned long long a,
                                                   unsigned long long b) {
    unsigned long long d;
    asm("add.rn.f32x2 %0, %1, %2;" : "=l"(d) : "l"(a), "l"(b));
    return d;
}
__device__ __forceinline__ float ex2f(float x) {
    float r; asm("ex2.approx.f32 %0, %1;" : "=f"(r) : "f"(x)); return r;
}
__device__ __forceinline__ float rcpf(float x) {
    float r; asm("rcp.approx.f32 %0, %1;" : "=f"(r) : "f"(x)); return r;
}
__device__ __forceinline__ float fast_sigmoid(float x) {       // plain domain
    return rcpf(1.0f + ex2f(x * NLOG2E));
}

// One CTA per TWO batches, 160 threads, grid 128 (one CTA/SM, single wave).
// Round 13: K-SPLIT PAIR. Thread (u = tid>>1, k = tid&1) owns ALL FOUR gate
// columns of unit u restricted to K-half k (h[32k..32k+31]): 4x16 = 64 f32x2
// weight regs. Per thread/step: 16 LDS.128 (vs 32 in R4 -> doubles effective
// MLP window), 128 fma2 (unchanged floor), 4 shfl_xor exchanging partial z's
// BEFORE the sigmoids (both directions useful per shfl), then a LANE-PARALLEL
// tail: lane k runs batch k's full gate nonlinearity locally (no gate
// exchange, tail issue per warp halved). Sigmoids in prescaled -log2e domain
// (weights pre-multiplied; j by -2log2e; forget bias folded; x/bias seed only
// on k=0 so the pair-sum counts it once).
// Threads 128..159 (warp 4): layer-1 (units=1) + dense for both batches
// (lane halves), one step lagged. One __syncthreads per step.
__global__ __launch_bounds__(160, 1)
void lstm_stack_kernel(const float* __restrict__ x,
                       const float* __restrict__ W0,
                       const float* __restrict__ b0,
                       const float* __restrict__ W1,
                       const float* __restrict__ b1,
                       const float* __restrict__ Wd,
                       const float* __restrict__ bd,
                       float* __restrict__ out)
{
    constexpr int T = 2048;
    constexpr int HP = 72;            // padded h row (bank-conflict-free STS)

    const int bb   = blockIdx.x;      // batch pair
    const int tid  = threadIdx.x;
    const int lane = tid & 31;
    const int wid  = tid >> 5;

    __shared__ __align__(16) float x_sh[2][T];
    __shared__ __align__(16) float h_sh[2][2][HP];   // [buffer][batch][unit(+pad)]
    __shared__ float red[5];
    __shared__ float inv_sh[2];

    // ---- Phase 0: load both x tiles, l2-normalize over time ----
    for (int bi = 0; bi < 2; ++bi) {
        const float* xb = x + (2 * bb + bi) * T;
        float ps = 0.f;
        for (int i = tid; i < T; i += 160) {
            float v = xb[i];
            x_sh[bi][i] = v;
            ps = fmaf(v, v, ps);
        }
        #pragma unroll
        for (int o = 16; o > 0; o >>= 1) ps += __shfl_xor_sync(FULL, ps, o);
        if (lane == 0) red[wid] = ps;
        __syncthreads();
        if (tid == 0) {
            float s = 0.f;
            #pragma unroll
            for (int i = 0; i < 5; ++i) s += red[i];
            inv_sh[bi] = rsqrtf(fmaxf(s, 1e-12f));
        }
        __syncthreads();               // also protects red[] reuse
    }
    {
        float i0 = inv_sh[0], i1 = inv_sh[1];
        for (int i = tid; i < T; i += 160) {
            x_sh[0][i] *= i0;
            x_sh[1][i] *= i1;
        }
    }
    if (tid < 2 * HP) ((float*)h_sh[0])[tid] = 0.f;   // h_{-1} = 0 (both batches)
    // (ordered by the sync at the top of the main loop)

    // ---- Per-thread persistent state / weights ----
    const int u = tid >> 1;
    const int k = tid & 1;              // K-half AND owned batch for the tail
    unsigned long long wf[4][16];       // [gate][pair within my K-half]
    float wxe[4], bze[4];               // x-weight / bias seeds (0 on k=1)
    float c0 = 0.f;                     // cell state of MY batch (k)

    // layer-1 (warp 4) state: lanes 0-15 -> batch0, 16-31 -> batch1
    const int l1b  = lane >> 4;
    const int l1g  = lane & 3;
    const int l1bk = (lane >> 2) & 3;
    float w1r[16];
    float w1h = 0.f, b1v = 0.f, wdv = 0.f, bdv = 0.f;
    float c1 = 0.f, h1 = 0.f;

    if (tid < 128) {
        #pragma unroll
        for (int g = 0; g < 4; ++g) {
            const float sc = (g == 1) ? N2LOG2E : NLOG2E;
            const int col = g * 64 + u;
            wxe[g] = (k == 0) ? (W0[col] * sc) : 0.f;
            bze[g] = (k == 0) ? ((b0[col] + (g == 2 ? 1.0f : 0.0f)) * sc) : 0.f;
            #pragma unroll
            for (int p = 0; p < 16; ++p) {
                const int row = 1 + 32 * k + 2 * p;
                wf[g][p] = pack2(W0[row * 256 + col] * sc,
                                 W0[(row + 1) * 256 + col] * sc);
            }
        }
    } else {
        #pragma unroll
        for (int j = 0; j < 16; ++j)
            w1r[j] = W1[(l1bk + 4 * j) * 4 + l1g];
        w1h = W1[64 * 4 + l1g];
        b1v = b1[l1g];
        wdv = Wd[0];
        bdv = bd[0];
    }

    // ---- Main recurrence: t = 0..T. Layer-0 active for t<T, layer-1
    // processes step t-1 (final iteration drains layer-1). ----
    #pragma unroll 1
    for (int t = 0; t <= T; ++t) {
        const int tt = (t < T) ? t : 0;
        const float xt0 = x_sh[0][tt];   // read-only prefetch
        const float xt1 = x_sh[1][tt];
        __syncthreads();                 // h_sh[t&1] = h_{t-1} now valid
        const int cur = t & 1;
        if (tid < 128) {
            if (t < T) {
                const ulonglong2* hp0 =
                    (const ulonglong2*)&h_sh[cur][0][k * 32];
                const ulonglong2* hp1 =
                    (const ulonglong2*)&h_sh[cur][1][k * 32];
                // 16 accumulator chains: [batch][gate] x {x-chain, y-chain}
                unsigned long long ax0[4], ay0[4], ax1[4], ay1[4];
                #pragma unroll
                for (int g = 0; g < 4; ++g) {
                    ax0[g] = pack2(fmaf(xt0, wxe[g], bze[g]), 0.f);
                    ax1[g] = pack2(fmaf(xt1, wxe[g], bze[g]), 0.f);
                    ay0[g] = pack2(0.f, 0.f);
                    ay1[g] = pack2(0.f, 0.f);
                }
                #pragma unroll
                for (int i = 0; i < 8; ++i) {
                    ulonglong2 hv0 = hp0[i];   // my K-half, batch 0
                    ulonglong2 hv1 = hp1[i];   // my K-half, batch 1
                    #pragma unroll
                    for (int g = 0; g < 4; ++g) {
                        ax0[g] = fma2(hv0.x, wf[g][2 * i],     ax0[g]);
                        ay0[g] = fma2(hv0.y, wf[g][2 * i + 1], ay0[g]);
                        ax1[g] = fma2(hv1.x, wf[g][2 * i],     ax1[g]);
                        ay1[g] = fma2(hv1.y, wf[g][2 * i + 1], ay1[g]);
                    }
                }
                // partial z per [batch][gate]
                float P0[4], P1[4];
                #pragma unroll
                for (int g = 0; g < 4; ++g) {
                    float lo, hi;
                    unpack2(add2(ax0[g], ay0[g]), lo, hi); P0[g] = lo + hi;
                    unpack2(add2(ax1[g], ay1[g]), lo, hi); P1[g] = lo + hi;
                }
                // exchange: send partner's-batch partial, receive my-batch
                // partial from partner. One shfl per gate, both directions
                // useful: lane k sends P[k^1][g], receives partner's P[k][g].
                float z[4];
                #pragma unroll
                for (int g = 0; g < 4; ++g) {
                    float send = k ? P0[g] : P1[g];
                    float own  = k ? P1[g] : P0[g];
                    float recv = __shfl_xor_sync(FULL, send, 1);
                    z[g] = own + recv;
                }
                // lane-parallel tail: lane k runs batch k. Scaled domain:
                // sigma(v) = rcp(1 + ex2(-v*log2e)), z already scaled.
                float si = rcpf(1.0f + ex2f(z[0]));
                float tj = fmaf(2.f, rcpf(1.0f + ex2f(z[1])), -1.f); // tanh(j)
                float sf = rcpf(1.0f + ex2f(z[2]));                  // fbias folded
                float so = rcpf(1.0f + ex2f(z[3]));
                c0 = fmaf(sf, c0, si * tj);
                float tc = fmaf(2.f, rcpf(1.0f + ex2f(c0 * N2LOG2E)), -1.f);
                h_sh[cur ^ 1][k][u] = so * tc;
            }
        } else {
            if (t >= 1) {
                // layer-1 for step s = t-1, input h_sh[cur][l1b]
                const float* hv = h_sh[cur][l1b];
                float p0 = 0.f, p1 = 0.f;
                #pragma unroll
                for (int j = 0; j < 8; ++j) {
                    p0 = fmaf(hv[l1bk + 4 * (2 * j)],     w1r[2 * j],     p0);
                    p1 = fmaf(hv[l1bk + 4 * (2 * j + 1)], w1r[2 * j + 1], p1);
                }
                float p = p0 + p1;
                p += __shfl_xor_sync(FULL, p, 4);    // stays within 16-lane half
                p += __shfl_xor_sync(FULL, p, 8);
                float z1 = fmaf(h1, w1h, p + b1v);

                float zz = (l1g == 2) ? (z1 + 1.0f) : z1;
                float sv = (l1g == 1) ? (zz + zz) : zz;
                float sg = fast_sigmoid(sv);
                float r  = (l1g == 1) ? fmaf(2.f, sg, -1.f) : sg;

                float ri = __shfl_sync(FULL, r, 0, 4);
                float rj = __shfl_sync(FULL, r, 1, 4);
                float rf = __shfl_sync(FULL, r, 2, 4);
                float ro = __shfl_sync(FULL, r, 3, 4);
                c1 = fmaf(rf, c1, ri * rj);
                float th = fmaf(2.f, fast_sigmoid(c1 + c1), -1.f);
                h1 = ro * th;
                if ((lane & 15) == 0)
                    out[(2 * bb + l1b) * T + (t - 1)] = fmaf(h1, wdv, bdv);
            }
        }
    }
}

extern "C" void kernel_launch(void* const* d_in, const int* in_sizes, int n_in,
                              void* d_out, int out_size) {
    const float* x  = (const float*)d_in[0];
    const float* W0 = (const float*)d_in[1];
    const float* b0 = (const float*)d_in[2];
    const float* W1 = (const float*)d_in[3];
    const float* b1 = (const float*)d_in[4];
    const float* Wd = (const float*)d_in[5];
    const float* bd = (const float*)d_in[6];
    float* out = (float*)d_out;
    lstm_stack_kernel<<<128, 160>>>(x, W0, b0, W1, b1, Wd, bd, out);
}

// round 14
// speedup vs baseline: 1.3747x; 1.1196x over previous
#include <cuda_runtime.h>

#define FULL 0xFFFFFFFFu

__device__ __forceinline__ unsigned long long pack2(float a, float b) {
    unsigned long long r;
    asm("mov.b64 %0, {%1, %2};" : "=l"(r) : "f"(a), "f"(b));
    return r;
}
__device__ __forceinline__ void unpack2(unsigned long long p, float& a, float& b) {
    asm("mov.b64 {%0, %1}, %2;" : "=f"(a), "=f"(b) : "l"(p));
}
__device__ __forceinline__ unsigned long long fma2(unsigned long long a,
                                                   unsigned long long b,
                                                   unsigned long long c) {
    unsigned long long d;
    asm("fma.rn.f32x2 %0, %1, %2, %3;" : "=l"(d) : "l"(a), "l"(b), "l"(c));
    return d;
}
__device__ __forceinline__ unsigned long long add2(unsigned long long a,
                                                   unsigned long long b) {
    unsigned long long d;
    asm("add.rn.f32x2 %0, %1, %2;" : "=l"(d) : "l"(a), "l"(b));
    return d;
}
__device__ __forceinline__ float tanh_ap(float x) {
    float r; asm("tanh.approx.f32 %0, %1;" : "=f"(r) : "f"(x)); return r;
}
// sigma from half-scaled argument zh = z/2 :  0.5*tanh(zh) + 0.5
__device__ __forceinline__ float sigmoid_half(float zh) {
    return fmaf(0.5f, tanh_ap(zh), 0.5f);
}

// One CTA per TWO batches, 160 threads, grid 128 (one CTA/SM, single wave).
// Round 14 = champion R13 with ONE change: all sigmoids/tanhs use the HW
// MUFU.TANH (tanh.approx.f32). sigma(z) = 0.5*tanh(z/2)+0.5 with the 1/2
// pre-folded into the i/f/o weight columns (j column unscaled: tanh direct).
// MUFU ops per thread/step drop 10 -> 5 and each sigmoid chain 41 -> 20 cyc.
// Layout (R13): thread (u = tid>>1, k = tid&1) owns all 4 gate columns of
// unit u restricted to K-half k; 16 LDS.128 + 128 fma2 per thread/step;
// 4 shfl_xor exchange partial z's BEFORE the nonlinearity; lane-parallel
// tail (lane k = batch k). Threads 128..159 (warp 4): layer-1 + dense for
// both batches (lane halves), one step lagged. One __syncthreads per step.
__global__ __launch_bounds__(160, 1)
void lstm_stack_kernel(const float* __restrict__ x,
                       const float* __restrict__ W0,
                       const float* __restrict__ b0,
                       const float* __restrict__ W1,
                       const float* __restrict__ b1,
                       const float* __restrict__ Wd,
                       const float* __restrict__ bd,
                       float* __restrict__ out)
{
    constexpr int T = 2048;
    constexpr int HP = 72;            // padded h row (bank-conflict-free STS)

    const int bb   = blockIdx.x;      // batch pair
    const int tid  = threadIdx.x;
    const int lane = tid & 31;
    const int wid  = tid >> 5;

    __shared__ __align__(16) float x_sh[2][T];
    __shared__ __align__(16) float h_sh[2][2][HP];   // [buffer][batch][unit(+pad)]
    __shared__ float red[5];
    __shared__ float inv_sh[2];

    // ---- Phase 0: load both x tiles, l2-normalize over time ----
    for (int bi = 0; bi < 2; ++bi) {
        const float* xb = x + (2 * bb + bi) * T;
        float ps = 0.f;
        for (int i = tid; i < T; i += 160) {
            float v = xb[i];
            x_sh[bi][i] = v;
            ps = fmaf(v, v, ps);
        }
        #pragma unroll
        for (int o = 16; o > 0; o >>= 1) ps += __shfl_xor_sync(FULL, ps, o);
        if (lane == 0) red[wid] = ps;
        __syncthreads();
        if (tid == 0) {
            float s = 0.f;
            #pragma unroll
            for (int i = 0; i < 5; ++i) s += red[i];
            inv_sh[bi] = rsqrtf(fmaxf(s, 1e-12f));
        }
        __syncthreads();               // also protects red[] reuse
    }
    {
        float i0 = inv_sh[0], i1 = inv_sh[1];
        for (int i = tid; i < T; i += 160) {
            x_sh[0][i] *= i0;
            x_sh[1][i] *= i1;
        }
    }
    if (tid < 2 * HP) ((float*)h_sh[0])[tid] = 0.f;   // h_{-1} = 0 (both batches)
    // (ordered by the sync at the top of the main loop)

    // ---- Per-thread persistent state / weights ----
    const int u = tid >> 1;
    const int k = tid & 1;              // K-half AND owned batch for the tail
    unsigned long long wf[4][16];       // [gate][pair within my K-half]
    float wxe[4], bze[4];               // x-weight / bias seeds (0 on k=1)
    float c0 = 0.f;                     // cell state of MY batch (k)

    // layer-1 (warp 4) state: lanes 0-15 -> batch0, 16-31 -> batch1
    const int l1b  = lane >> 4;
    const int l1g  = lane & 3;
    const int l1bk = (lane >> 2) & 3;
    float w1r[16];
    float w1h = 0.f, b1v = 0.f, wdv = 0.f, bdv = 0.f;
    float c1 = 0.f, h1 = 0.f;

    if (tid < 128) {
        #pragma unroll
        for (int g = 0; g < 4; ++g) {
            // i/f/o: fold sigma's 1/2 into the column; j: unscaled (tanh direct)
            const float sc = (g == 1) ? 1.0f : 0.5f;
            const int col = g * 64 + u;
            wxe[g] = (k == 0) ? (W0[col] * sc) : 0.f;
            bze[g] = (k == 0) ? ((b0[col] + (g == 2 ? 1.0f : 0.0f)) * sc) : 0.f;
            #pragma unroll
            for (int p = 0; p < 16; ++p) {
                const int row = 1 + 32 * k + 2 * p;
                wf[g][p] = pack2(W0[row * 256 + col] * sc,
                                 W0[(row + 1) * 256 + col] * sc);
            }
        }
    } else {
        #pragma unroll
        for (int j = 0; j < 16; ++j)
            w1r[j] = W1[(l1bk + 4 * j) * 4 + l1g];
        w1h = W1[64 * 4 + l1g];
        b1v = b1[l1g];
        wdv = Wd[0];
        bdv = bd[0];
    }

    // ---- Main recurrence: t = 0..T. Layer-0 active for t<T, layer-1
    // processes step t-1 (final iteration drains layer-1). ----
    #pragma unroll 1
    for (int t = 0; t <= T; ++t) {
        const int tt = (t < T) ? t : 0;
        const float xt0 = x_sh[0][tt];   // read-only prefetch
        const float xt1 = x_sh[1][tt];
        __syncthreads();                 // h_sh[t&1] = h_{t-1} now valid
        const int cur = t & 1;
        if (tid < 128) {
            if (t < T) {
                const ulonglong2* hp0 =
                    (const ulonglong2*)&h_sh[cur][0][k * 32];
                const ulonglong2* hp1 =
                    (const ulonglong2*)&h_sh[cur][1][k * 32];
                // 16 accumulator chains: [batch][gate] x {x-chain, y-chain}
                unsigned long long ax0[4], ay0[4], ax1[4], ay1[4];
                #pragma unroll
                for (int g = 0; g < 4; ++g) {
                    ax0[g] = pack2(fmaf(xt0, wxe[g], bze[g]), 0.f);
                    ax1[g] = pack2(fmaf(xt1, wxe[g], bze[g]), 0.f);
                    ay0[g] = pack2(0.f, 0.f);
                    ay1[g] = pack2(0.f, 0.f);
                }
                #pragma unroll
                for (int i = 0; i < 8; ++i) {
                    ulonglong2 hv0 = hp0[i];   // my K-half, batch 0
                    ulonglong2 hv1 = hp1[i];   // my K-half, batch 1
                    #pragma unroll
                    for (int g = 0; g < 4; ++g) {
                        ax0[g] = fma2(hv0.x, wf[g][2 * i],     ax0[g]);
                        ay0[g] = fma2(hv0.y, wf[g][2 * i + 1], ay0[g]);
                        ax1[g] = fma2(hv1.x, wf[g][2 * i],     ax1[g]);
                        ay1[g] = fma2(hv1.y, wf[g][2 * i + 1], ay1[g]);
                    }
                }
                // partial z per [batch][gate]
                float P0[4], P1[4];
                #pragma unroll
                for (int g = 0; g < 4; ++g) {
                    float lo, hi;
                    unpack2(add2(ax0[g], ay0[g]), lo, hi); P0[g] = lo + hi;
                    unpack2(add2(ax1[g], ay1[g]), lo, hi); P1[g] = lo + hi;
                }
                // exchange: one shfl per gate, both directions useful.
                float z[4];
                #pragma unroll
                for (int g = 0; g < 4; ++g) {
                    float send = k ? P0[g] : P1[g];
                    float own  = k ? P1[g] : P0[g];
                    float recv = __shfl_xor_sync(FULL, send, 1);
                    z[g] = own + recv;
                }
                // lane-parallel tail via HW tanh: lane k runs batch k.
                float si = sigmoid_half(z[0]);       // z pre-halved via weights
                float tj = tanh_ap(z[1]);            // j unscaled -> tanh direct
                float sf = sigmoid_half(z[2]);       // forget bias folded
                float so = sigmoid_half(z[3]);
                c0 = fmaf(sf, c0, si * tj);
                h_sh[cur ^ 1][k][u] = so * tanh_ap(c0);
            }
        } else {
            if (t >= 1) {
                // layer-1 for step s = t-1, input h_sh[cur][l1b]
                const float* hv = h_sh[cur][l1b];
                float p0 = 0.f, p1 = 0.f;
                #pragma unroll
                for (int j = 0; j < 8; ++j) {
                    p0 = fmaf(hv[l1bk + 4 * (2 * j)],     w1r[2 * j],     p0);
                    p1 = fmaf(hv[l1bk + 4 * (2 * j + 1)], w1r[2 * j + 1], p1);
                }
                float p = p0 + p1;
                p += __shfl_xor_sync(FULL, p, 4);    // stays within 16-lane half
                p += __shfl_xor_sync(FULL, p, 8);
                float z1 = fmaf(h1, w1h, p + b1v);

                float zz = (l1g == 2) ? (z1 + 1.0f) : z1;
                // gate: j -> tanh(z); i/f/o -> sigma(z) = 0.5*tanh(z/2)+0.5
                float r = (l1g == 1) ? tanh_ap(zz)
                                     : fmaf(0.5f, tanh_ap(0.5f * zz), 0.5f);

                float ri = __shfl_sync(FULL, r, 0, 4);
                float rj = __shfl_sync(FULL, r, 1, 4);
                float rf = __shfl_sync(FULL, r, 2, 4);
                float ro = __shfl_sync(FULL, r, 3, 4);
                c1 = fmaf(rf, c1, ri * rj);
                h1 = ro * tanh_ap(c1);
                if ((lane & 15) == 0)
                    out[(2 * bb + l1b) * T + (t - 1)] = fmaf(h1, wdv, bdv);
            }
        }
    }
}

extern "C" void kernel_launch(void* const* d_in, const int* in_sizes, int n_in,
                              void* d_out, int out_size) {
    const float* x  = (const float*)d_in[0];
    const float* W0 = (const float*)d_in[1];
    const float* b0 = (const float*)d_in[2];
    const float* W1 = (const float*)d_in[3];
    const float* b1 = (const float*)d_in[4];
    const float* Wd = (const float*)d_in[5];
    const float* bd = (const float*)d_in[6];
    float* out = (float*)d_out;
    lstm_stack_kernel<<<128, 160>>>(x, W0, b0, W1, b1, Wd, bd, out);
}

// round 15
// speedup vs baseline: 1.5138x; 1.1012x over previous
#include <cuda_runtime.h>

#define FULL 0xFFFFFFFFu

__device__ __forceinline__ unsigned long long pack2(float a, float b) {
    unsigned long long r;
    asm("mov.b64 %0, {%1, %2};" : "=l"(r) : "f"(a), "f"(b));
    return r;
}
__device__ __forceinline__ void unpack2(unsigned long long p, float& a, float& b) {
    asm("mov.b64 {%0, %1}, %2;" : "=f"(a), "=f"(b) : "l"(p));
}
__device__ __forceinline__ unsigned long long fma2(unsigned long long a,
                                                   unsigned long long b,
                                                   unsigned long long c) {
    unsigned long long d;
    asm("fma.rn.f32x2 %0, %1, %2, %3;" : "=l"(d) : "l"(a), "l"(b), "l"(c));
    return d;
}
__device__ __forceinline__ unsigned long long add2(unsigned long long a,
                                                   unsigned long long b) {
    unsigned long long d;
    asm("add.rn.f32x2 %0, %1, %2;" : "=l"(d) : "l"(a), "l"(b));
    return d;
}
__device__ __forceinline__ float tanh_ap(float x) {
    float r; asm("tanh.approx.f32 %0, %1;" : "=f"(r) : "f"(x)); return r;
}
// sigma from half-scaled argument zh = z/2 :  0.5*tanh(zh) + 0.5
__device__ __forceinline__ float sigmoid_half(float zh) {
    return fmaf(0.5f, tanh_ap(zh), 0.5f);
}

// One CTA per TWO batches, 160 threads, grid 128 (one CTA/SM, single wave).
// Round 15 = champion R14 (K-split pair + MUFU.TANH nonlinearities) plus:
//  (1) explicit depth-1 software pipeline on the h-broadcast LDS: iteration
//      i+1's two LDS.128 issue BEFORE iteration i's 16 fma2, so the 29-cycle
//      shared-memory latency hides under 32 cycles of fma issue instead of
//      being exposed at ptxas's just-in-time load placement;
//  (2) peeled step loop (t=0 layer-0 only / 1..T-1 both / T layer-1 drain)
//      removing per-step predicates from the hot path.
// Layout: thread (u = tid>>1, k = tid&1) owns all 4 gate columns of unit u
// restricted to K-half k; 16 LDS.128 + 128 fma2 per thread/step; 4 shfl_xor
// exchange partial z's; lane-parallel tail (lane k = batch k); sigma's 1/2
// pre-folded into i/f/o weights. Threads 128..159 (warp 4): layer-1 + dense
// for both batches (lane halves), one step lagged. One __syncthreads/step.
__global__ __launch_bounds__(160, 1)
void lstm_stack_kernel(const float* __restrict__ x,
                       const float* __restrict__ W0,
                       const float* __restrict__ b0,
                       const float* __restrict__ W1,
                       const float* __restrict__ b1,
                       const float* __restrict__ Wd,
                       const float* __restrict__ bd,
                       float* __restrict__ out)
{
    constexpr int T = 2048;
    constexpr int HP = 72;            // padded h row (bank-conflict-free STS)

    const int bb   = blockIdx.x;      // batch pair
    const int tid  = threadIdx.x;
    const int lane = tid & 31;
    const int wid  = tid >> 5;

    __shared__ __align__(16) float x_sh[2][T];
    __shared__ __align__(16) float h_sh[2][2][HP];   // [buffer][batch][unit(+pad)]
    __shared__ float red[5];
    __shared__ float inv_sh[2];

    // ---- Phase 0: load both x tiles, l2-normalize over time ----
    for (int bi = 0; bi < 2; ++bi) {
        const float* xb = x + (2 * bb + bi) * T;
        float ps = 0.f;
        for (int i = tid; i < T; i += 160) {
            float v = xb[i];
            x_sh[bi][i] = v;
            ps = fmaf(v, v, ps);
        }
        #pragma unroll
        for (int o = 16; o > 0; o >>= 1) ps += __shfl_xor_sync(FULL, ps, o);
        if (lane == 0) red[wid] = ps;
        __syncthreads();
        if (tid == 0) {
            float s = 0.f;
            #pragma unroll
            for (int i = 0; i < 5; ++i) s += red[i];
            inv_sh[bi] = rsqrtf(fmaxf(s, 1e-12f));
        }
        __syncthreads();               // also protects red[] reuse
    }
    {
        float i0 = inv_sh[0], i1 = inv_sh[1];
        for (int i = tid; i < T; i += 160) {
            x_sh[0][i] *= i0;
            x_sh[1][i] *= i1;
        }
    }
    if (tid < 2 * HP) ((float*)h_sh[0])[tid] = 0.f;   // h_{-1} = 0 (both batches)
    // (ordered by the first __syncthreads in the main sequence)

    // ---- Per-thread persistent state / weights ----
    const int u = tid >> 1;
    const int k = tid & 1;              // K-half AND owned batch for the tail
    unsigned long long wf[4][16];       // [gate][pair within my K-half]
    float wxe[4], bze[4];               // x-weight / bias seeds (0 on k=1)
    float c0 = 0.f;                     // cell state of MY batch (k)

    // layer-1 (warp 4) state: lanes 0-15 -> batch0, 16-31 -> batch1
    const int l1b  = lane >> 4;
    const int l1g  = lane & 3;
    const int l1bk = (lane >> 2) & 3;
    float w1r[16];
    float w1h = 0.f, b1v = 0.f, wdv = 0.f, bdv = 0.f;
    float c1 = 0.f, h1 = 0.f;

    if (tid < 128) {
        #pragma unroll
        for (int g = 0; g < 4; ++g) {
            // i/f/o: fold sigma's 1/2 into the column; j: unscaled (tanh direct)
            const float sc = (g == 1) ? 1.0f : 0.5f;
            const int col = g * 64 + u;
            wxe[g] = (k == 0) ? (W0[col] * sc) : 0.f;
            bze[g] = (k == 0) ? ((b0[col] + (g == 2 ? 1.0f : 0.0f)) * sc) : 0.f;
            #pragma unroll
            for (int p = 0; p < 16; ++p) {
                const int row = 1 + 32 * k + 2 * p;
                wf[g][p] = pack2(W0[row * 256 + col] * sc,
                                 W0[(row + 1) * 256 + col] * sc);
            }
        }
    } else {
        #pragma unroll
        for (int j = 0; j < 16; ++j)
            w1r[j] = W1[(l1bk + 4 * j) * 4 + l1g];
        w1h = W1[64 * 4 + l1g];
        b1v = b1[l1g];
        wdv = Wd[0];
        bdv = bd[0];
    }

    // ---- Step bodies ----
    auto layer0_step = [&](int t) {
        const int cur = t & 1;
        const float xt0 = x_sh[0][t];
        const float xt1 = x_sh[1][t];
        const ulonglong2* hp0 = (const ulonglong2*)&h_sh[cur][0][k * 32];
        const ulonglong2* hp1 = (const ulonglong2*)&h_sh[cur][1][k * 32];
        // 16 accumulator chains: [batch][gate] x {x-chain, y-chain}
        unsigned long long ax0[4], ay0[4], ax1[4], ay1[4];
        #pragma unroll
        for (int g = 0; g < 4; ++g) {
            ax0[g] = pack2(fmaf(xt0, wxe[g], bze[g]), 0.f);
            ax1[g] = pack2(fmaf(xt1, wxe[g], bze[g]), 0.f);
            ay0[g] = pack2(0.f, 0.f);
            ay1[g] = pack2(0.f, 0.f);
        }
        // depth-1 software pipeline: next iteration's LDS issues before
        // this iteration's 16 fma2 (32 issue cyc cover the 29-cyc latency)
        ulonglong2 hv0 = hp0[0];
        ulonglong2 hv1 = hp1[0];
        #pragma unroll
        for (int i = 0; i < 8; ++i) {
            ulonglong2 nv0, nv1;
            if (i < 7) { nv0 = hp0[i + 1]; nv1 = hp1[i + 1]; }
            #pragma unroll
            for (int g = 0; g < 4; ++g) {
                ax0[g] = fma2(hv0.x, wf[g][2 * i],     ax0[g]);
                ay0[g] = fma2(hv0.y, wf[g][2 * i + 1], ay0[g]);
                ax1[g] = fma2(hv1.x, wf[g][2 * i],     ax1[g]);
                ay1[g] = fma2(hv1.y, wf[g][2 * i + 1], ay1[g]);
            }
            if (i < 7) { hv0 = nv0; hv1 = nv1; }
        }
        // partial z per [batch][gate]
        float P0[4], P1[4];
        #pragma unroll
        for (int g = 0; g < 4; ++g) {
            float lo, hi;
            unpack2(add2(ax0[g], ay0[g]), lo, hi); P0[g] = lo + hi;
            unpack2(add2(ax1[g], ay1[g]), lo, hi); P1[g] = lo + hi;
        }
        // exchange: one shfl per gate, both directions useful.
        float z[4];
        #pragma unroll
        for (int g = 0; g < 4; ++g) {
            float send = k ? P0[g] : P1[g];
            float own  = k ? P1[g] : P0[g];
            float recv = __shfl_xor_sync(FULL, send, 1);
            z[g] = own + recv;
        }
        // lane-parallel tail via HW tanh: lane k runs batch k.
        float si = sigmoid_half(z[0]);       // z pre-halved via weights
        float tj = tanh_ap(z[1]);            // j unscaled -> tanh direct
        float sf = sigmoid_half(z[2]);       // forget bias folded
        float so = sigmoid_half(z[3]);
        c0 = fmaf(sf, c0, si * tj);
        h_sh[cur ^ 1][k][u] = so * tanh_ap(c0);
    };

    auto layer1_step = [&](int s) {          // computes layer-1 step s
        const int buf = (s + 1) & 1;         // h_sh[buf] holds h^{(0)}(s)
        const float* hv = h_sh[buf][l1b];
        float p0 = 0.f, p1 = 0.f;
        #pragma unroll
        for (int j = 0; j < 8; ++j) {
            p0 = fmaf(hv[l1bk + 4 * (2 * j)],     w1r[2 * j],     p0);
            p1 = fmaf(hv[l1bk + 4 * (2 * j + 1)], w1r[2 * j + 1], p1);
        }
        float p = p0 + p1;
        p += __shfl_xor_sync(FULL, p, 4);    // stays within 16-lane half
        p += __shfl_xor_sync(FULL, p, 8);
        float z1 = fmaf(h1, w1h, p + b1v);

        float zz = (l1g == 2) ? (z1 + 1.0f) : z1;
        // gate: j -> tanh(z); i/f/o -> sigma(z) = 0.5*tanh(z/2)+0.5
        float r = (l1g == 1) ? tanh_ap(zz)
                             : fmaf(0.5f, tanh_ap(0.5f * zz), 0.5f);

        float ri = __shfl_sync(FULL, r, 0, 4);
        float rj = __shfl_sync(FULL, r, 1, 4);
        float rf = __shfl_sync(FULL, r, 2, 4);
        float ro = __shfl_sync(FULL, r, 3, 4);
        c1 = fmaf(rf, c1, ri * rj);
        h1 = ro * tanh_ap(c1);
        if ((lane & 15) == 0)
            out[(2 * bb + l1b) * T + s] = fmaf(h1, wdv, bdv);
    };

    // ---- Peeled main sequence ----
    __syncthreads();                      // orders phase-0 writes + h init
    if (tid < 128) layer0_step(0);
    #pragma unroll 1
    for (int t = 1; t < T; ++t) {
        __syncthreads();                  // publishes h(t-1)
        if (tid < 128) layer0_step(t);
        else           layer1_step(t - 1);
    }
    __syncthreads();                      // publishes h(T-1)
    if (tid >= 128) layer1_step(T - 1);   // drain
}

extern "C" void kernel_launch(void* const* d_in, const int* in_sizes, int n_in,
                              void* d_out, int out_size) {
    const float* x  = (const float*)d_in[0];
    const float* W0 = (const float*)d_in[1];
    const float* b0 = (const float*)d_in[2];
    const float* W1 = (const float*)d_in[3];
    const float* b1 = (const float*)d_in[4];
    const float* Wd = (const float*)d_in[5];
    const float* bd = (const float*)d_in[6];
    float* out = (float*)d_out;
    lstm_stack_kernel<<<128, 160>>>(x, W0, b0, W1, b1, Wd, bd, out);
}